// round 1
// baseline (speedup 1.0000x reference)
#include <cuda_runtime.h>
#include <math.h>

// ---------------- problem constants ----------------
#define NTOK 32768          // N
#define CDIM 256            // C
#define NHD  8              // heads
#define HD   32             // head dim
#define AGN  64             // agent tokens
#define FD   32             // cube side
#define PD   34             // padded side
#define PVOL (34*34*34)     // 39304
#define KCONV (27*256)      // 6912

// ---------------- scratch (device globals, no allocs) ----------------
__device__ float g_lin[NTOK*768];            // qkv output (N, 3C)
__device__ float g_S[NHD*AGN*NTOK];          // stage-1 logits
__device__ float g_m[NHD*AGN];
__device__ float g_l[NHD*AGN];
__device__ float g_A[AGN*CDIM];              // agent tokens (AG, C)
__device__ float g_avpart[64*NHD*AGN*HD];    // partial agent_v sums
__device__ float g_av[NHD*AGN*HD];           // agent_v (normalized)
__device__ float g_mid[NTOK*CDIM];           // attention out + conv (B,N,C)
__device__ float g_vpad[PVOL*CDIM];          // zero-padded v volume, channel-fastest
__device__ float g_wtqkv[256*768];           // w_qkv^T  (K,N)
__device__ float g_wtproj[256*256];          // w_proj^T (K,N)
__device__ float g_wtconv[KCONV*256];        // conv weights as (K=tap*256+ci, co)

// ---------------- small prep kernels ----------------
__global__ void k_tr_qkv(const float* __restrict__ w, float* __restrict__ wt) {
    int idx = blockIdx.x * 256 + threadIdx.x;           // 768*256
    int n = idx >> 8, k = idx & 255;
    wt[k * 768 + n] = w[n * 256 + k];
}
__global__ void k_tr_proj(const float* __restrict__ w, float* __restrict__ wt) {
    int idx = blockIdx.x * 256 + threadIdx.x;           // 256*256
    int n = idx >> 8, k = idx & 255;
    wt[k * 256 + n] = w[n * 256 + k];
}
__global__ void k_tr_conv(const float* __restrict__ w, float* __restrict__ wt) {
    // wt[(tap*256+ci)*256 + co] = w[(co*256+ci)*27 + tap]
    int idx = blockIdx.x * 256 + threadIdx.x;           // 27*256*256
    int co  = idx & 255;
    int r   = idx >> 8;            // tap*256+ci
    int ci  = r & 255;
    int tap = r >> 8;
    wt[idx] = w[(co * 256 + ci) * 27 + tap];
}
__global__ void k_zero(float* __restrict__ p, int n) {
    int i = blockIdx.x * 256 + threadIdx.x;
    if (i < n) p[i] = 0.0f;
}

// ---------------- generic GEMM: C = A(M,K) @ Bt(K,N) + bias, optional += ----------------
__global__ void __launch_bounds__(256) gemm_kernel(
    const float* __restrict__ A, int lda,
    const float* __restrict__ Bt, int N,
    const float* __restrict__ bias,
    float* __restrict__ C, int ldc, int K, int accum)
{
    __shared__ float As[16][64];
    __shared__ float Bs[16][64];
    const int m0 = blockIdx.y * 64, n0 = blockIdx.x * 64;
    const int tid = threadIdx.x;
    const int tx = tid & 15, ty = tid >> 4;
    const int lm = tid >> 2, lkg = tid & 3;
    const int lbk = tid >> 4, lbn = tid & 15;
    const float* Ap = A + (size_t)(m0 + lm) * lda + lkg * 4;

    float acc[4][4];
#pragma unroll
    for (int i = 0; i < 4; i++)
#pragma unroll
        for (int j = 0; j < 4; j++) acc[i][j] = 0.0f;

    for (int k0 = 0; k0 < K; k0 += 16) {
        float4 a4 = *(const float4*)(Ap + k0);
        As[lkg * 4 + 0][lm] = a4.x;
        As[lkg * 4 + 1][lm] = a4.y;
        As[lkg * 4 + 2][lm] = a4.z;
        As[lkg * 4 + 3][lm] = a4.w;
        *(float4*)&Bs[lbk][lbn * 4] =
            *(const float4*)&Bt[(size_t)(k0 + lbk) * N + n0 + lbn * 4];
        __syncthreads();
#pragma unroll
        for (int kk = 0; kk < 16; kk++) {
            const float4 a = *(const float4*)&As[kk][ty * 4];
            const float4 b = *(const float4*)&Bs[kk][tx * 4];
            acc[0][0] += a.x*b.x; acc[0][1] += a.x*b.y; acc[0][2] += a.x*b.z; acc[0][3] += a.x*b.w;
            acc[1][0] += a.y*b.x; acc[1][1] += a.y*b.y; acc[1][2] += a.y*b.z; acc[1][3] += a.y*b.w;
            acc[2][0] += a.z*b.x; acc[2][1] += a.z*b.y; acc[2][2] += a.z*b.z; acc[2][3] += a.z*b.w;
            acc[3][0] += a.w*b.x; acc[3][1] += a.w*b.y; acc[3][2] += a.w*b.z; acc[3][3] += a.w*b.w;
        }
        __syncthreads();
    }
    const float4 bv = *(const float4*)&bias[n0 + tx * 4];
#pragma unroll
    for (int i = 0; i < 4; i++) {
        float* cp = &C[(size_t)(m0 + ty * 4 + i) * ldc + n0 + tx * 4];
        if (accum) {
            cp[0] += acc[i][0] + bv.x;
            cp[1] += acc[i][1] + bv.y;
            cp[2] += acc[i][2] + bv.z;
            cp[3] += acc[i][3] + bv.w;
        } else {
            float4 o; o.x = acc[i][0] + bv.x; o.y = acc[i][1] + bv.y;
            o.z = acc[i][2] + bv.z; o.w = acc[i][3] + bv.w;
            *(float4*)cp = o;
        }
    }
}

// ---------------- conv implicit GEMM: mid += vpad_gather @ wtconv + b_dwc ----------------
__global__ void __launch_bounds__(256) conv_gemm_kernel(
    const float* __restrict__ vpad,
    const float* __restrict__ Bt,   // (6912, 256)
    const float* __restrict__ bias,
    float* __restrict__ C)          // mid, ldc=256, accumulate
{
    __shared__ float As[16][64];
    __shared__ float Bs[16][64];
    const int m0 = blockIdx.y * 64, n0 = blockIdx.x * 64;
    const int tid = threadIdx.x;
    const int tx = tid & 15, ty = tid >> 4;
    const int lm = tid >> 2, lkg = tid & 3;
    const int lbk = tid >> 4, lbn = tid & 15;

    const int m = m0 + lm;
    const int x = m >> 10, y = (m >> 5) & 31, z = m & 31;
    const int base = ((x + 1) * 34 + (y + 1)) * 34 + (z + 1);

    float acc[4][4];
#pragma unroll
    for (int i = 0; i < 4; i++)
#pragma unroll
        for (int j = 0; j < 4; j++) acc[i][j] = 0.0f;

    for (int tap = 0; tap < 27; tap++) {
        const int kx = tap / 9, ky = (tap / 3) % 3, kz = tap % 3;
        const float* Apt = vpad +
            (size_t)(base + (kx - 1) * 1156 + (ky - 1) * 34 + (kz - 1)) * 256 + lkg * 4;
        const float* Bpt = Bt + (size_t)(tap * 256) * 256;
        for (int kc = 0; kc < 256; kc += 16) {
            float4 a4 = *(const float4*)(Apt + kc);
            As[lkg * 4 + 0][lm] = a4.x;
            As[lkg * 4 + 1][lm] = a4.y;
            As[lkg * 4 + 2][lm] = a4.z;
            As[lkg * 4 + 3][lm] = a4.w;
            *(float4*)&Bs[lbk][lbn * 4] =
                *(const float4*)&Bpt[(size_t)(kc + lbk) * 256 + n0 + lbn * 4];
            __syncthreads();
#pragma unroll
            for (int kk = 0; kk < 16; kk++) {
                const float4 a = *(const float4*)&As[kk][ty * 4];
                const float4 b = *(const float4*)&Bs[kk][tx * 4];
                acc[0][0] += a.x*b.x; acc[0][1] += a.x*b.y; acc[0][2] += a.x*b.z; acc[0][3] += a.x*b.w;
                acc[1][0] += a.y*b.x; acc[1][1] += a.y*b.y; acc[1][2] += a.y*b.z; acc[1][3] += a.y*b.w;
                acc[2][0] += a.z*b.x; acc[2][1] += a.z*b.y; acc[2][2] += a.z*b.z; acc[2][3] += a.z*b.w;
                acc[3][0] += a.w*b.x; acc[3][1] += a.w*b.y; acc[3][2] += a.w*b.z; acc[3][3] += a.w*b.w;
            }
            __syncthreads();
        }
    }
    const float4 bv = *(const float4*)&bias[n0 + tx * 4];
#pragma unroll
    for (int i = 0; i < 4; i++) {
        float* cp = &C[(size_t)(m0 + ty * 4 + i) * 256 + n0 + tx * 4];
        cp[0] += acc[i][0] + bv.x;
        cp[1] += acc[i][1] + bv.y;
        cp[2] += acc[i][2] + bv.z;
        cp[3] += acc[i][3] + bv.w;
    }
}

// ---------------- agent-token pooling ----------------
// A[a][c] = mean over 8^3 block of q_vol[f1,f2,f3,c]
// q_vol[f1,f2,f3,c] = lin[(f1&3)*8192 + f2*256 + f3*8 + (c>>5)][ (f1>>2)*32 + (c&31) ]
__global__ void k_pool(const float* __restrict__ lin, float* __restrict__ A) {
    const int a = blockIdx.x;        // 64
    const int c = threadIdx.x;       // 256
    const int p1 = a >> 4, p2 = (a >> 2) & 3, p3 = a & 3;
    const int csub = c >> 5;
    float s = 0.0f;
    for (int b1 = 0; b1 < 8; b1++) {
        const int f1 = p1 * 8 + b1;
        const int ch = (f1 >> 2) * 32 + (c & 31);
        const int nb1 = (f1 & 3) * 8192;
        for (int b2 = 0; b2 < 8; b2++) {
            const int nb2 = nb1 + (p2 * 8 + b2) * 256;
            for (int b3 = 0; b3 < 8; b3++) {
                const int n = nb2 + (p3 * 8 + b3) * 8 + csub;
                s += lin[(size_t)n * 768 + ch];
            }
        }
    }
    A[a * 256 + c] = s * (1.0f / 512.0f);
}

// ---------------- stage-1 logits: S[h][a][n] = scale * A_h[a]·k_h[n] ----------------
__global__ void __launch_bounds__(256) k_S(const float* __restrict__ lin,
                                           const float* __restrict__ Amat,
                                           float* __restrict__ S) {
    const int h = blockIdx.y;
    const int n = blockIdx.x * 256 + threadIdx.x;
    __shared__ float4 As[64][8];
    for (int e = threadIdx.x; e < 512; e += 256) {
        int a = e >> 3, dq = e & 7;
        As[a][dq] = *(const float4*)&Amat[a * 256 + h * 32 + dq * 4];
    }
    __syncthreads();
    float4 kv[8];
    const float* kp = lin + (size_t)n * 768 + 256 + h * 32;
#pragma unroll
    for (int i = 0; i < 8; i++) kv[i] = *(const float4*)&kp[i * 4];
    const float scale = 0.17677669529663687f;
    float* Sp = S + (size_t)(h * 64) * NTOK + n;
#pragma unroll 4
    for (int a = 0; a < 64; a++) {
        float s = 0.0f;
#pragma unroll
        for (int i = 0; i < 8; i++) {
            const float4 av = As[a][i];
            s += kv[i].x * av.x + kv[i].y * av.y + kv[i].z * av.z + kv[i].w * av.w;
        }
        Sp[(size_t)a * NTOK] = s * scale;
    }
}

// ---------------- per-row max / sumexp ----------------
__global__ void k_rowstat(const float* __restrict__ S, float* __restrict__ m,
                          float* __restrict__ l) {
    const int r = blockIdx.x;
    const float* Sr = S + (size_t)r * NTOK;
    __shared__ float red[256];
    float mx = -1e30f;
    for (int i = threadIdx.x; i < NTOK; i += 256) mx = fmaxf(mx, Sr[i]);
    red[threadIdx.x] = mx; __syncthreads();
    for (int s = 128; s > 0; s >>= 1) {
        if (threadIdx.x < s) red[threadIdx.x] = fmaxf(red[threadIdx.x], red[threadIdx.x + s]);
        __syncthreads();
    }
    mx = red[0]; __syncthreads();
    float sum = 0.0f;
    for (int i = threadIdx.x; i < NTOK; i += 256) sum += __expf(Sr[i] - mx);
    red[threadIdx.x] = sum; __syncthreads();
    for (int s = 128; s > 0; s >>= 1) {
        if (threadIdx.x < s) red[threadIdx.x] += red[threadIdx.x + s];
        __syncthreads();
    }
    if (threadIdx.x == 0) { m[r] = mx; l[r] = red[0]; }
}

// ---------------- agent_v partials: part[chunk][h][a][d] ----------------
__global__ void __launch_bounds__(256) k_agentv(const float* __restrict__ lin,
                                                const float* __restrict__ S,
                                                const float* __restrict__ m,
                                                float* __restrict__ part) {
    const int h = blockIdx.y;
    const int chunk = blockIdx.x;            // 64 chunks of 512 tokens
    const int n0 = chunk * 512;
    __shared__ float Ss[64][64];
    __shared__ float vs[64][32];
    const int a = threadIdx.x >> 2, dg = threadIdx.x & 3;
    const float m_a = m[h * 64 + a];
    float acc[8];
#pragma unroll
    for (int j = 0; j < 8; j++) acc[j] = 0.0f;

    for (int sub = 0; sub < 8; sub++) {
        const int nb = n0 + sub * 64;
        for (int e = threadIdx.x; e < 1024; e += 256) {
            int aa = e >> 4, tq = e & 15;
            *(float4*)&Ss[aa][tq * 4] =
                *(const float4*)&S[(size_t)(h * 64 + aa) * NTOK + nb + tq * 4];
        }
        for (int e = threadIdx.x; e < 512; e += 256) {
            int t = e >> 3, dq = e & 7;
            *(float4*)&vs[t][dq * 4] =
                *(const float4*)&lin[(size_t)(nb + t) * 768 + 512 + h * 32 + dq * 4];
        }
        __syncthreads();
#pragma unroll 8
        for (int t = 0; t < 64; t++) {
            const float p = __expf(Ss[a][t] - m_a);
#pragma unroll
            for (int j = 0; j < 8; j++) acc[j] += p * vs[t][dg * 8 + j];
        }
        __syncthreads();
    }
    float* pp = part + (size_t)((chunk * 8 + h) * 64 + a) * 32 + dg * 8;
#pragma unroll
    for (int j = 0; j < 8; j++) pp[j] = acc[j];
}

__global__ void k_avreduce(const float* __restrict__ part, const float* __restrict__ l,
                           float* __restrict__ av) {
    const int idx = blockIdx.x * 256 + threadIdx.x;      // 16384
    float s = 0.0f;
    for (int ch = 0; ch < 64; ch++) s += part[(size_t)ch * 16384 + idx];
    av[idx] = s / l[idx >> 5];
}

// ---------------- stage 2: per-token softmax over agents, scatter to mid ----------------
__global__ void __launch_bounds__(256) k_stage2(const float* __restrict__ lin,
                                                const float* __restrict__ Amat,
                                                const float* __restrict__ av,
                                                float* __restrict__ mid) {
    const int h = blockIdx.y;
    const int n = blockIdx.x * 256 + threadIdx.x;
    __shared__ float4 As[64][8];
    __shared__ float4 Vs[64][8];
    for (int e = threadIdx.x; e < 512; e += 256) {
        int a = e >> 3, dq = e & 7;
        As[a][dq] = *(const float4*)&Amat[a * 256 + h * 32 + dq * 4];
        Vs[a][dq] = *(const float4*)&av[(size_t)(h * 64 + a) * 32 + dq * 4];
    }
    __syncthreads();
    float4 qv[8];
    const float* qp = lin + (size_t)n * 768 + h * 32;
#pragma unroll
    for (int i = 0; i < 8; i++) qv[i] = *(const float4*)&qp[i * 4];
    const float scale = 0.17677669529663687f;
    float lg[64];
    float mx = -1e30f;
#pragma unroll
    for (int a = 0; a < 64; a++) {
        float s = 0.0f;
#pragma unroll
        for (int i = 0; i < 8; i++) {
            const float4 v = As[a][i];
            s += qv[i].x * v.x + qv[i].y * v.y + qv[i].z * v.z + qv[i].w * v.w;
        }
        s *= scale;
        lg[a] = s;
        mx = fmaxf(mx, s);
    }
    float sum = 0.0f;
#pragma unroll
    for (int a = 0; a < 64; a++) {
        const float p = __expf(lg[a] - mx);
        lg[a] = p;
        sum += p;
    }
    float4 o[8];
#pragma unroll
    for (int i = 0; i < 8; i++) { o[i].x = 0; o[i].y = 0; o[i].z = 0; o[i].w = 0; }
#pragma unroll
    for (int a = 0; a < 64; a++) {
        const float p = lg[a];
#pragma unroll
        for (int i = 0; i < 8; i++) {
            const float4 v = Vs[a][i];
            o[i].x += p * v.x; o[i].y += p * v.y; o[i].z += p * v.z; o[i].w += p * v.w;
        }
    }
    const float inv = 1.0f / sum;
    // faithful torch scramble: mid_flat[h*1048576 + d*32768 + n]
    float* mp = mid + (size_t)h * 1048576 + n;
#pragma unroll
    for (int i = 0; i < 8; i++) {
        mp[(size_t)(i * 4 + 0) * NTOK] = o[i].x * inv;
        mp[(size_t)(i * 4 + 1) * NTOK] = o[i].y * inv;
        mp[(size_t)(i * 4 + 2) * NTOK] = o[i].z * inv;
        mp[(size_t)(i * 4 + 3) * NTOK] = o[i].w * inv;
    }
}

// ---------------- vpad fill: vpad[(x+1,y+1,z+1)][c] = v[n][c] ----------------
__global__ void k_vpadfill(const float* __restrict__ lin, float* __restrict__ vpad) {
    const int n = blockIdx.x;
    const int c4 = threadIdx.x;      // 64 threads => float4 each
    const int x = n >> 10, y = (n >> 5) & 31, z = n & 31;
    const int p = ((x + 1) * 34 + (y + 1)) * 34 + (z + 1);
    *(float4*)&vpad[(size_t)p * 256 + c4 * 4] =
        *(const float4*)&lin[(size_t)n * 768 + 512 + c4 * 4];
}

// ---------------- launch ----------------
extern "C" void kernel_launch(void* const* d_in, const int* in_sizes, int n_in,
                              void* d_out, int out_size) {
    const float* x      = (const float*)d_in[0];
    const float* w_qkv  = (const float*)d_in[1];
    const float* b_qkv  = (const float*)d_in[2];
    const float* w_proj = (const float*)d_in[3];
    const float* b_proj = (const float*)d_in[4];
    const float* w_dwc  = (const float*)d_in[5];
    const float* b_dwc  = (const float*)d_in[6];
    float* out = (float*)d_out;

    float *lin, *S, *m, *l, *A, *avpart, *av, *mid, *vpad, *wtqkv, *wtproj, *wtconv;
    cudaGetSymbolAddress((void**)&lin,    g_lin);
    cudaGetSymbolAddress((void**)&S,      g_S);
    cudaGetSymbolAddress((void**)&m,      g_m);
    cudaGetSymbolAddress((void**)&l,      g_l);
    cudaGetSymbolAddress((void**)&A,      g_A);
    cudaGetSymbolAddress((void**)&avpart, g_avpart);
    cudaGetSymbolAddress((void**)&av,     g_av);
    cudaGetSymbolAddress((void**)&mid,    g_mid);
    cudaGetSymbolAddress((void**)&vpad,   g_vpad);
    cudaGetSymbolAddress((void**)&wtqkv,  g_wtqkv);
    cudaGetSymbolAddress((void**)&wtproj, g_wtproj);
    cudaGetSymbolAddress((void**)&wtconv, g_wtconv);

    // prep
    k_tr_qkv<<<768, 256>>>(w_qkv, wtqkv);
    k_tr_proj<<<256, 256>>>(w_proj, wtproj);
    k_tr_conv<<<6912, 256>>>(w_dwc, wtconv);
    k_zero<<<(PVOL * CDIM + 255) / 256, 256>>>(vpad, PVOL * CDIM);

    // qkv projection
    gemm_kernel<<<dim3(12, 512), 256>>>(x, 256, wtqkv, 768, b_qkv, lin, 768, 256, 0);

    // agent tokens
    k_pool<<<64, 256>>>(lin, A);

    // stage 1
    k_S<<<dim3(128, 8), 256>>>(lin, A, S);
    k_rowstat<<<512, 256>>>(S, m, l);
    k_agentv<<<dim3(64, 8), 256>>>(lin, S, m, avpart);
    k_avreduce<<<64, 256>>>(avpart, l, av);

    // stage 2 -> mid (attention part, full coverage)
    k_stage2<<<dim3(128, 8), 256>>>(lin, A, av, mid);

    // conv residual: pad v, implicit GEMM accumulate into mid
    k_vpadfill<<<NTOK, 64>>>(lin, vpad);
    conv_gemm_kernel<<<dim3(4, 512), 256>>>(vpad, wtconv, b_dwc, mid);

    // output projection
    gemm_kernel<<<dim3(4, 512), 256>>>(mid, 256, wtproj, 256, b_proj, out, 256, 256, 0);
}

// round 3
// speedup vs baseline: 2.0925x; 2.0925x over previous
#include <cuda_runtime.h>
#include <cuda_bf16.h>
#include <math.h>
#include <cstdint>

// ---------------- problem constants ----------------
#define NTOK 32768
#define CDIM 256
#define NHD  8
#define HD   32
#define AGN  64
#define PVOL (34*34*34)
#define KCONV (27*256)

// ---------------- scratch (device globals) ----------------
__device__ float g_lin[NTOK * 768];
__device__ float g_S[NHD * AGN * NTOK];
__device__ float g_m[NHD * AGN];
__device__ float g_l[NHD * AGN];
__device__ float g_A[AGN * CDIM];
__device__ float g_avpart[64 * NHD * AGN * HD];
__device__ float g_av[NHD * AGN * HD];
__device__ float g_mid[NTOK * CDIM];
__device__ __nv_bfloat16 g_xhi[NTOK * CDIM], g_xlo[NTOK * CDIM];
__device__ __nv_bfloat16 g_mhi[NTOK * CDIM], g_mlo[NTOK * CDIM];
__device__ __nv_bfloat16 g_vph[PVOL * CDIM], g_vpl[PVOL * CDIM];
__device__ __nv_bfloat16 g_wqh[768 * 256], g_wql[768 * 256];
__device__ __nv_bfloat16 g_wph[256 * 256], g_wpl[256 * 256];
__device__ __nv_bfloat16 g_wch[256 * KCONV], g_wcl[256 * KCONV];

// ---------------- asm helpers (sm_80-era, compile on plain compute_103) ----
__device__ __forceinline__ uint32_t smem_u32(const void* p) {
    uint32_t a;
    asm("{ .reg .u64 t; cvta.to.shared.u64 t, %1; cvt.u32.u64 %0, t; }" : "=r"(a) : "l"(p));
    return a;
}
#define CP16(dst, src) \
    asm volatile("cp.async.cg.shared.global [%0], [%1], 16;" :: "r"(dst), "l"(src))
#define CP_COMMIT() asm volatile("cp.async.commit_group;")
#define CP_WAIT1()  asm volatile("cp.async.wait_group 1;")
#define CP_WAIT0()  asm volatile("cp.async.wait_group 0;")

#define LDSM4(r, addr) \
    asm volatile("ldmatrix.sync.aligned.m8n8.x4.shared.b16 {%0,%1,%2,%3}, [%4];" \
        : "=r"((r)[0]), "=r"((r)[1]), "=r"((r)[2]), "=r"((r)[3]) : "r"(addr))

#define MMA16816(d, a, b0v, b1v) \
    asm volatile("mma.sync.aligned.m16n8k16.row.col.f32.bf16.bf16.f32 " \
        "{%0,%1,%2,%3}, {%4,%5,%6,%7}, {%8,%9}, {%0,%1,%2,%3};" \
        : "+f"((d)[0]), "+f"((d)[1]), "+f"((d)[2]), "+f"((d)[3]) \
        : "r"((a)[0]), "r"((a)[1]), "r"((a)[2]), "r"((a)[3]), "r"(b0v), "r"(b1v))

// ---------------- conversion kernels ----------------
__global__ void k_split(const float* __restrict__ x, __nv_bfloat16* __restrict__ hi,
                        __nv_bfloat16* __restrict__ lo, int n) {
    int i = blockIdx.x * 256 + threadIdx.x;
    if (i < n) {
        float v = x[i];
        __nv_bfloat16 h = __float2bfloat16(v);
        hi[i] = h;
        lo[i] = __float2bfloat16(v - __bfloat162float(h));
    }
}
__global__ void k_wconv(const float* __restrict__ w, __nv_bfloat16* __restrict__ hi,
                        __nv_bfloat16* __restrict__ lo) {
    int i = blockIdx.x * 256 + threadIdx.x;     // 27*256*256
    int co = i / KCONV;
    int rem = i - co * KCONV;
    int tap = rem >> 8, ci = rem & 255;
    float v = w[(co * 256 + ci) * 27 + tap];
    __nv_bfloat16 h = __float2bfloat16(v);
    hi[i] = h;
    lo[i] = __float2bfloat16(v - __bfloat162float(h));
}
__global__ void k_zero_b(uint32_t* __restrict__ p, int n) {
    int i = blockIdx.x * 256 + threadIdx.x;
    if (i < n) p[i] = 0u;
}
__global__ void k_vpadsplit(const float* __restrict__ lin, __nv_bfloat16* __restrict__ hi,
                            __nv_bfloat16* __restrict__ lo) {
    const int n = blockIdx.x;
    const int c4 = threadIdx.x;     // 64
    const int x = n >> 10, y = (n >> 5) & 31, z = n & 31;
    const int p = ((x + 1) * 34 + (y + 1)) * 34 + (z + 1);
    float4 v = *(const float4*)&lin[(size_t)n * 768 + 512 + c4 * 4];
    size_t o = (size_t)p * 256 + c4 * 4;
    float a[4] = {v.x, v.y, v.z, v.w};
#pragma unroll
    for (int j = 0; j < 4; j++) {
        __nv_bfloat16 h = __float2bfloat16(a[j]);
        hi[o + j] = h;
        lo[o + j] = __float2bfloat16(a[j] - __bfloat162float(h));
    }
}

// ---------------- HMMA split-bf16 GEMM ----------------
// C(MT*128, NT*128) = (Ahi+Alo)(M,K) @ (Bhi+Blo)(Nrows,K)^T + bias
// mode 0: dense A rows (stride K). mode 1: conv implicit gather from vpad.
// smem: per buffer AH(0) AL(10240) BH(20480) BL(30720); row stride 80B; 2 buffers.
#define TILE_B 10240
#define BUF_B  40960
#define SMEM_TOT (2 * BUF_B)

__global__ void __launch_bounds__(256) gemm_mma(
    const __nv_bfloat16* __restrict__ Ahi, const __nv_bfloat16* __restrict__ Alo,
    const __nv_bfloat16* __restrict__ Bhi, const __nv_bfloat16* __restrict__ Blo,
    const float* __restrict__ bias, float* __restrict__ C,
    int K, int ldc, int mode, int accum)
{
    extern __shared__ char smem[];
    const uint32_t sb = smem_u32(smem);
    const int t = threadIdx.x;
    const int m0 = blockIdx.y * 128, n0 = blockIdx.x * 128;
    const int seg = t & 3, r0 = t >> 2;              // load roles
    const int wid = t >> 5, lane = t & 31;
    const int wy = wid >> 1, wx = wid & 1;           // warp grid 4x2
    const int lA_r = lane & 15, lA_k8 = (lane >> 4) & 1;
    const int lB_n = (lane & 7) + ((lane >> 4) & 1) * 8, lB_k8 = (lane >> 3) & 1;
    const int NC = K >> 5;

    float acc[2][8][4];
#pragma unroll
    for (int i = 0; i < 2; i++)
#pragma unroll
        for (int j = 0; j < 8; j++)
#pragma unroll
            for (int q = 0; q < 4; q++) acc[i][j][q] = 0.0f;

    auto prefetch = [&](int c, int buf) {
        const uint32_t bb = sb + buf * BUF_B;
        const int kc = c * 32;
        int dx = 0, dy = 0, dz = 0;
        const int ci0 = kc & 255;
        if (mode) {
            const int tap = kc >> 8;
            dx = tap / 9 - 1; dy = (tap / 3) % 3 - 1; dz = tap % 3 - 1;
        }
#pragma unroll
        for (int i = 0; i < 2; i++) {
            const int r = r0 + i * 64;
            const uint32_t so = r * 80 + seg * 16;
            size_t aoff;
            if (!mode) {
                aoff = (size_t)(m0 + r) * K + kc + seg * 8;
            } else {
                const int m = m0 + r;
                const int x = m >> 10, y = (m >> 5) & 31, z = m & 31;
                aoff = (size_t)(((x + 1 + dx) * 34 + (y + 1 + dy)) * 34 + (z + 1 + dz)) * 256
                       + ci0 + seg * 8;
            }
            CP16(bb + so, Ahi + aoff);
            CP16(bb + TILE_B + so, Alo + aoff);
            const size_t boff = (size_t)(n0 + r) * K + kc + seg * 8;
            CP16(bb + 2 * TILE_B + so, Bhi + boff);
            CP16(bb + 3 * TILE_B + so, Blo + boff);
        }
        CP_COMMIT();
    };

    prefetch(0, 0);
    for (int c = 0; c < NC; c++) {
        if (c + 1 < NC) { prefetch(c + 1, (c + 1) & 1); CP_WAIT1(); }
        else CP_WAIT0();
        __syncthreads();
        const uint32_t bb = sb + (c & 1) * BUF_B;
#pragma unroll
        for (int ks = 0; ks < 2; ks++) {
            uint32_t ah[2][4], al[2][4];
#pragma unroll
            for (int mt = 0; mt < 2; mt++) {
                const uint32_t aaddr = bb + (wy * 32 + mt * 16 + lA_r) * 80
                                       + (ks * 16 + lA_k8 * 8) * 2;
                LDSM4(ah[mt], aaddr);
                LDSM4(al[mt], aaddr + TILE_B);
            }
            uint32_t bh[4][4], bl[4][4];
#pragma unroll
            for (int np = 0; np < 4; np++) {
                const uint32_t baddr = bb + 2 * TILE_B + (wx * 64 + np * 16 + lB_n) * 80
                                       + (ks * 16 + lB_k8 * 8) * 2;
                LDSM4(bh[np], baddr);
                LDSM4(bl[np], baddr + TILE_B);
            }
#pragma unroll
            for (int mt = 0; mt < 2; mt++)
#pragma unroll
                for (int nt = 0; nt < 8; nt++) {
                    const uint32_t* bp = &bh[nt >> 1][(nt & 1) * 2];
                    const uint32_t* blp = &bl[nt >> 1][(nt & 1) * 2];
                    MMA16816(acc[mt][nt], ah[mt], bp[0], bp[1]);
                    MMA16816(acc[mt][nt], ah[mt], blp[0], blp[1]);
                    MMA16816(acc[mt][nt], al[mt], bp[0], bp[1]);
                }
        }
        __syncthreads();
    }

    // epilogue
    const int er = lane >> 2, ec = (lane & 3) * 2;
#pragma unroll
    for (int mt = 0; mt < 2; mt++) {
        const int row = m0 + wy * 32 + mt * 16 + er;
#pragma unroll
        for (int nt = 0; nt < 8; nt++) {
            const int col = n0 + wx * 64 + nt * 8 + ec;
            const float b0 = __ldg(&bias[col]), b1 = __ldg(&bias[col + 1]);
            float* cp0 = C + (size_t)row * ldc + col;
            float* cp1 = C + (size_t)(row + 8) * ldc + col;
            if (accum) {
                cp0[0] += acc[mt][nt][0] + b0;
                cp0[1] += acc[mt][nt][1] + b1;
                cp1[0] += acc[mt][nt][2] + b0;
                cp1[1] += acc[mt][nt][3] + b1;
            } else {
                cp0[0] = acc[mt][nt][0] + b0;
                cp0[1] = acc[mt][nt][1] + b1;
                cp1[0] = acc[mt][nt][2] + b0;
                cp1[1] = acc[mt][nt][3] + b1;
            }
        }
    }
}

// ---------------- scalar attention kernels ----------------
__global__ void k_pool(const float* __restrict__ lin, float* __restrict__ A) {
    const int a = blockIdx.x;
    const int c = threadIdx.x;
    const int p1 = a >> 4, p2 = (a >> 2) & 3, p3 = a & 3;
    const int csub = c >> 5;
    float s = 0.0f;
    for (int b1 = 0; b1 < 8; b1++) {
        const int f1 = p1 * 8 + b1;
        const int ch = (f1 >> 2) * 32 + (c & 31);
        const int nb1 = (f1 & 3) * 8192;
        for (int b2 = 0; b2 < 8; b2++) {
            const int nb2 = nb1 + (p2 * 8 + b2) * 256;
            for (int b3 = 0; b3 < 8; b3++) {
                const int n = nb2 + (p3 * 8 + b3) * 8 + csub;
                s += lin[(size_t)n * 768 + ch];
            }
        }
    }
    A[a * 256 + c] = s * (1.0f / 512.0f);
}

__global__ void __launch_bounds__(256) k_S(const float* __restrict__ lin,
                                           const float* __restrict__ Amat,
                                           float* __restrict__ S) {
    const int h = blockIdx.y;
    const int n = blockIdx.x * 256 + threadIdx.x;
    __shared__ float4 As[64][8];
    for (int e = threadIdx.x; e < 512; e += 256) {
        int a = e >> 3, dq = e & 7;
        As[a][dq] = *(const float4*)&Amat[a * 256 + h * 32 + dq * 4];
    }
    __syncthreads();
    float4 kv[8];
    const float* kp = lin + (size_t)n * 768 + 256 + h * 32;
#pragma unroll
    for (int i = 0; i < 8; i++) kv[i] = *(const float4*)&kp[i * 4];
    const float scale = 0.17677669529663687f;
    float* Sp = S + (size_t)(h * 64) * NTOK + n;
#pragma unroll 4
    for (int a = 0; a < 64; a++) {
        float s = 0.0f;
#pragma unroll
        for (int i = 0; i < 8; i++) {
            const float4 av = As[a][i];
            s += kv[i].x * av.x + kv[i].y * av.y + kv[i].z * av.z + kv[i].w * av.w;
        }
        Sp[(size_t)a * NTOK] = s * scale;
    }
}

__global__ void k_rowstat(const float* __restrict__ S, float* __restrict__ m,
                          float* __restrict__ l) {
    const int r = blockIdx.x;
    const float* Sr = S + (size_t)r * NTOK;
    __shared__ float red[256];
    float mx = -1e30f;
    for (int i = threadIdx.x; i < NTOK; i += 256) mx = fmaxf(mx, Sr[i]);
    red[threadIdx.x] = mx; __syncthreads();
    for (int s = 128; s > 0; s >>= 1) {
        if (threadIdx.x < s) red[threadIdx.x] = fmaxf(red[threadIdx.x], red[threadIdx.x + s]);
        __syncthreads();
    }
    mx = red[0]; __syncthreads();
    float sum = 0.0f;
    for (int i = threadIdx.x; i < NTOK; i += 256) sum += __expf(Sr[i] - mx);
    red[threadIdx.x] = sum; __syncthreads();
    for (int s = 128; s > 0; s >>= 1) {
        if (threadIdx.x < s) red[threadIdx.x] += red[threadIdx.x + s];
        __syncthreads();
    }
    if (threadIdx.x == 0) { m[r] = mx; l[r] = red[0]; }
}

__global__ void __launch_bounds__(256) k_agentv(const float* __restrict__ lin,
                                                const float* __restrict__ S,
                                                const float* __restrict__ m,
                                                float* __restrict__ part) {
    const int h = blockIdx.y;
    const int chunk = blockIdx.x;
    const int n0 = chunk * 512;
    __shared__ float Ss[64][64];
    __shared__ float vs[64][32];
    const int a = threadIdx.x >> 2, dg = threadIdx.x & 3;
    const float m_a = m[h * 64 + a];
    float acc[8];
#pragma unroll
    for (int j = 0; j < 8; j++) acc[j] = 0.0f;

    for (int sub = 0; sub < 8; sub++) {
        const int nb = n0 + sub * 64;
        for (int e = threadIdx.x; e < 1024; e += 256) {
            int aa = e >> 4, tq = e & 15;
            *(float4*)&Ss[aa][tq * 4] =
                *(const float4*)&S[(size_t)(h * 64 + aa) * NTOK + nb + tq * 4];
        }
        for (int e = threadIdx.x; e < 512; e += 256) {
            int tt = e >> 3, dq = e & 7;
            *(float4*)&vs[tt][dq * 4] =
                *(const float4*)&lin[(size_t)(nb + tt) * 768 + 512 + h * 32 + dq * 4];
        }
        __syncthreads();
#pragma unroll 8
        for (int tt = 0; tt < 64; tt++) {
            const float p = __expf(Ss[a][tt] - m_a);
#pragma unroll
            for (int j = 0; j < 8; j++) acc[j] += p * vs[tt][dg * 8 + j];
        }
        __syncthreads();
    }
    float* pp = part + (size_t)((chunk * 8 + h) * 64 + a) * 32 + dg * 8;
#pragma unroll
    for (int j = 0; j < 8; j++) pp[j] = acc[j];
}

__global__ void k_avreduce(const float* __restrict__ part, const float* __restrict__ l,
                           float* __restrict__ av) {
    const int idx = blockIdx.x * 256 + threadIdx.x;
    float s = 0.0f;
    for (int ch = 0; ch < 64; ch++) s += part[(size_t)ch * 16384 + idx];
    av[idx] = s / l[idx >> 5];
}

__global__ void __launch_bounds__(256) k_stage2(const float* __restrict__ lin,
                                                const float* __restrict__ Amat,
                                                const float* __restrict__ av,
                                                float* __restrict__ mid) {
    const int h = blockIdx.y;
    const int n = blockIdx.x * 256 + threadIdx.x;
    __shared__ float4 As[64][8];
    __shared__ float4 Vs[64][8];
    for (int e = threadIdx.x; e < 512; e += 256) {
        int a = e >> 3, dq = e & 7;
        As[a][dq] = *(const float4*)&Amat[a * 256 + h * 32 + dq * 4];
        Vs[a][dq] = *(const float4*)&av[(size_t)(h * 64 + a) * 32 + dq * 4];
    }
    __syncthreads();
    float4 qv[8];
    const float* qp = lin + (size_t)n * 768 + h * 32;
#pragma unroll
    for (int i = 0; i < 8; i++) qv[i] = *(const float4*)&qp[i * 4];
    const float scale = 0.17677669529663687f;
    float lg[64];
    float mx = -1e30f;
#pragma unroll
    for (int a = 0; a < 64; a++) {
        float s = 0.0f;
#pragma unroll
        for (int i = 0; i < 8; i++) {
            const float4 v = As[a][i];
            s += qv[i].x * v.x + qv[i].y * v.y + qv[i].z * v.z + qv[i].w * v.w;
        }
        s *= scale;
        lg[a] = s;
        mx = fmaxf(mx, s);
    }
    float sum = 0.0f;
#pragma unroll
    for (int a = 0; a < 64; a++) {
        const float p = __expf(lg[a] - mx);
        lg[a] = p;
        sum += p;
    }
    float4 o[8];
#pragma unroll
    for (int i = 0; i < 8; i++) { o[i].x = 0; o[i].y = 0; o[i].z = 0; o[i].w = 0; }
#pragma unroll
    for (int a = 0; a < 64; a++) {
        const float p = lg[a];
#pragma unroll
        for (int i = 0; i < 8; i++) {
            const float4 v = Vs[a][i];
            o[i].x += p * v.x; o[i].y += p * v.y; o[i].z += p * v.z; o[i].w += p * v.w;
        }
    }
    const float inv = 1.0f / sum;
    float* mp = mid + (size_t)h * 1048576 + n;
#pragma unroll
    for (int i = 0; i < 8; i++) {
        mp[(size_t)(i * 4 + 0) * NTOK] = o[i].x * inv;
        mp[(size_t)(i * 4 + 1) * NTOK] = o[i].y * inv;
        mp[(size_t)(i * 4 + 2) * NTOK] = o[i].z * inv;
        mp[(size_t)(i * 4 + 3) * NTOK] = o[i].w * inv;
    }
}

// ---------------- launch ----------------
extern "C" void kernel_launch(void* const* d_in, const int* in_sizes, int n_in,
                              void* d_out, int out_size) {
    const float* x      = (const float*)d_in[0];
    const float* w_qkv  = (const float*)d_in[1];
    const float* b_qkv  = (const float*)d_in[2];
    const float* w_proj = (const float*)d_in[3];
    const float* b_proj = (const float*)d_in[4];
    const float* w_dwc  = (const float*)d_in[5];
    const float* b_dwc  = (const float*)d_in[6];
    float* out = (float*)d_out;

    float *lin, *S, *m, *l, *A, *avpart, *av, *mid;
    __nv_bfloat16 *xhi, *xlo, *mhi, *mlo, *vph, *vpl, *wqh, *wql, *wph, *wpl, *wch, *wcl;
    cudaGetSymbolAddress((void**)&lin,    g_lin);
    cudaGetSymbolAddress((void**)&S,      g_S);
    cudaGetSymbolAddress((void**)&m,      g_m);
    cudaGetSymbolAddress((void**)&l,      g_l);
    cudaGetSymbolAddress((void**)&A,      g_A);
    cudaGetSymbolAddress((void**)&avpart, g_avpart);
    cudaGetSymbolAddress((void**)&av,     g_av);
    cudaGetSymbolAddress((void**)&mid,    g_mid);
    cudaGetSymbolAddress((void**)&xhi,    g_xhi);
    cudaGetSymbolAddress((void**)&xlo,    g_xlo);
    cudaGetSymbolAddress((void**)&mhi,    g_mhi);
    cudaGetSymbolAddress((void**)&mlo,    g_mlo);
    cudaGetSymbolAddress((void**)&vph,    g_vph);
    cudaGetSymbolAddress((void**)&vpl,    g_vpl);
    cudaGetSymbolAddress((void**)&wqh,    g_wqh);
    cudaGetSymbolAddress((void**)&wql,    g_wql);
    cudaGetSymbolAddress((void**)&wph,    g_wph);
    cudaGetSymbolAddress((void**)&wpl,    g_wpl);
    cudaGetSymbolAddress((void**)&wch,    g_wch);
    cudaGetSymbolAddress((void**)&wcl,    g_wcl);

    cudaFuncSetAttribute(gemm_mma, cudaFuncAttributeMaxDynamicSharedMemorySize, SMEM_TOT);

    // splits
    k_split<<<(NTOK * CDIM + 255) / 256, 256>>>(x, xhi, xlo, NTOK * CDIM);
    k_split<<<(768 * 256 + 255) / 256, 256>>>(w_qkv, wqh, wql, 768 * 256);
    k_split<<<(256 * 256 + 255) / 256, 256>>>(w_proj, wph, wpl, 256 * 256);
    k_wconv<<<(27 * 256 * 256) / 256, 256>>>(w_dwc, wch, wcl);
    k_zero_b<<<(PVOL * CDIM / 2 + 255) / 256, 256>>>((uint32_t*)vph, PVOL * CDIM / 2);
    k_zero_b<<<(PVOL * CDIM / 2 + 255) / 256, 256>>>((uint32_t*)vpl, PVOL * CDIM / 2);

    // qkv projection: lin = x @ w_qkv^T + b
    gemm_mma<<<dim3(6, 256), 256, SMEM_TOT>>>(xhi, xlo, wqh, wql, b_qkv, lin, 256, 768, 0, 0);

    // attention
    k_pool<<<64, 256>>>(lin, A);
    k_S<<<dim3(128, 8), 256>>>(lin, A, S);
    k_rowstat<<<512, 256>>>(S, m, l);
    k_agentv<<<dim3(64, 8), 256>>>(lin, S, m, avpart);
    k_avreduce<<<64, 256>>>(avpart, l, av);
    k_stage2<<<dim3(128, 8), 256>>>(lin, A, av, mid);

    // conv residual (implicit GEMM), accumulate into mid
    k_vpadsplit<<<NTOK, 64>>>(lin, vph, vpl);
    gemm_mma<<<dim3(2, 256), 256, SMEM_TOT>>>(vph, vpl, wch, wcl, b_dwc, mid, KCONV, 256, 1, 1);

    // output projection
    k_split<<<(NTOK * CDIM + 255) / 256, 256>>>(mid, mhi, mlo, NTOK * CDIM);
    gemm_mma<<<dim3(2, 256), 256, SMEM_TOT>>>(mhi, mlo, wph, wpl, b_proj, out, 256, 256, 0, 0);
}

// round 4
// speedup vs baseline: 2.1056x; 1.0063x over previous
#include <cuda_runtime.h>
#include <cuda_bf16.h>
#include <math.h>
#include <cstdint>

// ---------------- problem constants ----------------
#define NTOK 32768
#define CDIM 256
#define NHD  8
#define HD   32
#define AGN  64
#define PVOL (34*34*34)
#define KCONV (27*256)

// ---------------- scratch (device globals) ----------------
__device__ float g_lin[NTOK * 768];
__device__ float g_S[NHD * AGN * NTOK];
__device__ float g_m[NHD * AGN];
__device__ float g_l[NHD * AGN];
__device__ float g_A[AGN * CDIM];
__device__ float g_avpart[64 * NHD * AGN * HD];
__device__ float g_av[NHD * AGN * HD];
__device__ float g_mid[NTOK * CDIM];
__device__ __nv_bfloat16 g_xhi[NTOK * CDIM], g_xlo[NTOK * CDIM];
__device__ __nv_bfloat16 g_mhi[NTOK * CDIM], g_mlo[NTOK * CDIM];
__device__ __nv_bfloat16 g_vph[PVOL * CDIM], g_vpl[PVOL * CDIM];
__device__ __nv_bfloat16 g_wqh[768 * 256], g_wql[768 * 256];
__device__ __nv_bfloat16 g_wph[256 * 256], g_wpl[256 * 256];
__device__ __nv_bfloat16 g_wch[256 * KCONV], g_wcl[256 * KCONV];

// ---------------- fast exp: FMA-pipe polynomial, no MUFU ----------------
__device__ __forceinline__ float fexp(float x) {
    float t = x * 1.4426950408889634f;
    int e = __float2int_rn(t);
    float f = t - (float)e;
    float p = 1.3333558e-3f;
    p = fmaf(p, f, 9.6181291e-3f);
    p = fmaf(p, f, 5.5504109e-2f);
    p = fmaf(p, f, 2.4022651e-1f);
    p = fmaf(p, f, 6.9314718e-1f);
    p = fmaf(p, f, 1.0f);
    return __int_as_float(__float_as_int(p) + (e << 23));
}

// ---------------- asm helpers ----------------
__device__ __forceinline__ uint32_t smem_u32(const void* p) {
    uint32_t a;
    asm("{ .reg .u64 t; cvta.to.shared.u64 t, %1; cvt.u32.u64 %0, t; }" : "=r"(a) : "l"(p));
    return a;
}
#define CP16(dst, src) \
    asm volatile("cp.async.cg.shared.global [%0], [%1], 16;" :: "r"(dst), "l"(src))
#define CP_COMMIT() asm volatile("cp.async.commit_group;")
#define CP_WAIT1()  asm volatile("cp.async.wait_group 1;")
#define CP_WAIT0()  asm volatile("cp.async.wait_group 0;")

#define LDSM4(r, addr) \
    asm volatile("ldmatrix.sync.aligned.m8n8.x4.shared.b16 {%0,%1,%2,%3}, [%4];" \
        : "=r"((r)[0]), "=r"((r)[1]), "=r"((r)[2]), "=r"((r)[3]) : "r"(addr))

#define MMA16816(d, a, b0v, b1v) \
    asm volatile("mma.sync.aligned.m16n8k16.row.col.f32.bf16.bf16.f32 " \
        "{%0,%1,%2,%3}, {%4,%5,%6,%7}, {%8,%9}, {%0,%1,%2,%3};" \
        : "+f"((d)[0]), "+f"((d)[1]), "+f"((d)[2]), "+f"((d)[3]) \
        : "r"((a)[0]), "r"((a)[1]), "r"((a)[2]), "r"((a)[3]), "r"(b0v), "r"(b1v))

// ---------------- conversion kernels ----------------
__global__ void k_split(const float* __restrict__ x, __nv_bfloat16* __restrict__ hi,
                        __nv_bfloat16* __restrict__ lo, int n) {
    int i = blockIdx.x * 256 + threadIdx.x;
    if (i < n) {
        float v = x[i];
        __nv_bfloat16 h = __float2bfloat16(v);
        hi[i] = h;
        lo[i] = __float2bfloat16(v - __bfloat162float(h));
    }
}
__global__ void k_wconv(const float* __restrict__ w, __nv_bfloat16* __restrict__ hi,
                        __nv_bfloat16* __restrict__ lo) {
    int i = blockIdx.x * 256 + threadIdx.x;     // 27*256*256
    int co = i / KCONV;
    int rem = i - co * KCONV;
    int tap = rem >> 8, ci = rem & 255;
    float v = w[(co * 256 + ci) * 27 + tap];
    __nv_bfloat16 h = __float2bfloat16(v);
    hi[i] = h;
    lo[i] = __float2bfloat16(v - __bfloat162float(h));
}
__global__ void k_zero_b(uint32_t* __restrict__ p, int n) {
    int i = blockIdx.x * 256 + threadIdx.x;
    if (i < n) p[i] = 0u;
}
__global__ void k_vpadsplit(const float* __restrict__ lin, __nv_bfloat16* __restrict__ hi,
                            __nv_bfloat16* __restrict__ lo) {
    const int n = blockIdx.x;
    const int c4 = threadIdx.x;     // 64
    const int x = n >> 10, y = (n >> 5) & 31, z = n & 31;
    const int p = ((x + 1) * 34 + (y + 1)) * 34 + (z + 1);
    float4 v = *(const float4*)&lin[(size_t)n * 768 + 512 + c4 * 4];
    size_t o = (size_t)p * 256 + c4 * 4;
    float a[4] = {v.x, v.y, v.z, v.w};
#pragma unroll
    for (int j = 0; j < 4; j++) {
        __nv_bfloat16 h = __float2bfloat16(a[j]);
        hi[o + j] = h;
        lo[o + j] = __float2bfloat16(a[j] - __bfloat162float(h));
    }
}

// ---------------- HMMA split-bf16 GEMM ----------------
#define TILE_B 10240
#define BUF_B  40960
#define SMEM_TOT (2 * BUF_B)

__global__ void __launch_bounds__(256) gemm_mma(
    const __nv_bfloat16* __restrict__ Ahi, const __nv_bfloat16* __restrict__ Alo,
    const __nv_bfloat16* __restrict__ Bhi, const __nv_bfloat16* __restrict__ Blo,
    const float* __restrict__ bias, float* __restrict__ C,
    int K, int ldc, int mode, int accum)
{
    extern __shared__ char smem[];
    const uint32_t sb = smem_u32(smem);
    const int t = threadIdx.x;
    const int m0 = blockIdx.y * 128, n0 = blockIdx.x * 128;
    const int seg = t & 3, r0 = t >> 2;
    const int wid = t >> 5, lane = t & 31;
    const int wy = wid >> 1, wx = wid & 1;
    const int lA_r = lane & 15, lA_k8 = (lane >> 4) & 1;
    const int lB_n = (lane & 7) + ((lane >> 4) & 1) * 8, lB_k8 = (lane >> 3) & 1;
    const int NC = K >> 5;

    float acc[2][8][4];
#pragma unroll
    for (int i = 0; i < 2; i++)
#pragma unroll
        for (int j = 0; j < 8; j++)
#pragma unroll
            for (int q = 0; q < 4; q++) acc[i][j][q] = 0.0f;

    auto prefetch = [&](int c, int buf) {
        const uint32_t bb = sb + buf * BUF_B;
        const int kc = c * 32;
        int dx = 0, dy = 0, dz = 0;
        const int ci0 = kc & 255;
        if (mode) {
            const int tap = kc >> 8;
            dx = tap / 9 - 1; dy = (tap / 3) % 3 - 1; dz = tap % 3 - 1;
        }
#pragma unroll
        for (int i = 0; i < 2; i++) {
            const int r = r0 + i * 64;
            const uint32_t so = r * 80 + seg * 16;
            size_t aoff;
            if (!mode) {
                aoff = (size_t)(m0 + r) * K + kc + seg * 8;
            } else {
                const int m = m0 + r;
                const int x = m >> 10, y = (m >> 5) & 31, z = m & 31;
                aoff = (size_t)(((x + 1 + dx) * 34 + (y + 1 + dy)) * 34 + (z + 1 + dz)) * 256
                       + ci0 + seg * 8;
            }
            CP16(bb + so, Ahi + aoff);
            CP16(bb + TILE_B + so, Alo + aoff);
            const size_t boff = (size_t)(n0 + r) * K + kc + seg * 8;
            CP16(bb + 2 * TILE_B + so, Bhi + boff);
            CP16(bb + 3 * TILE_B + so, Blo + boff);
        }
        CP_COMMIT();
    };

    prefetch(0, 0);
    for (int c = 0; c < NC; c++) {
        if (c + 1 < NC) { prefetch(c + 1, (c + 1) & 1); CP_WAIT1(); }
        else CP_WAIT0();
        __syncthreads();
        const uint32_t bb = sb + (c & 1) * BUF_B;
#pragma unroll
        for (int ks = 0; ks < 2; ks++) {
            uint32_t ah[2][4], al[2][4];
#pragma unroll
            for (int mt = 0; mt < 2; mt++) {
                const uint32_t aaddr = bb + (wy * 32 + mt * 16 + lA_r) * 80
                                       + (ks * 16 + lA_k8 * 8) * 2;
                LDSM4(ah[mt], aaddr);
                LDSM4(al[mt], aaddr + TILE_B);
            }
            uint32_t bh[4][4], bl[4][4];
#pragma unroll
            for (int np = 0; np < 4; np++) {
                const uint32_t baddr = bb + 2 * TILE_B + (wx * 64 + np * 16 + lB_n) * 80
                                       + (ks * 16 + lB_k8 * 8) * 2;
                LDSM4(bh[np], baddr);
                LDSM4(bl[np], baddr + TILE_B);
            }
#pragma unroll
            for (int mt = 0; mt < 2; mt++)
#pragma unroll
                for (int nt = 0; nt < 8; nt++) {
                    const uint32_t* bp = &bh[nt >> 1][(nt & 1) * 2];
                    const uint32_t* blp = &bl[nt >> 1][(nt & 1) * 2];
                    MMA16816(acc[mt][nt], ah[mt], bp[0], bp[1]);
                    MMA16816(acc[mt][nt], ah[mt], blp[0], blp[1]);
                    MMA16816(acc[mt][nt], al[mt], bp[0], bp[1]);
                }
        }
        __syncthreads();
    }

    const int er = lane >> 2, ec = (lane & 3) * 2;
#pragma unroll
    for (int mt = 0; mt < 2; mt++) {
        const int row = m0 + wy * 32 + mt * 16 + er;
#pragma unroll
        for (int nt = 0; nt < 8; nt++) {
            const int col = n0 + wx * 64 + nt * 8 + ec;
            const float b0 = __ldg(&bias[col]), b1 = __ldg(&bias[col + 1]);
            float* cp0 = C + (size_t)row * ldc + col;
            float* cp1 = C + (size_t)(row + 8) * ldc + col;
            if (accum) {
                cp0[0] += acc[mt][nt][0] + b0;
                cp0[1] += acc[mt][nt][1] + b1;
                cp1[0] += acc[mt][nt][2] + b0;
                cp1[1] += acc[mt][nt][3] + b1;
            } else {
                cp0[0] = acc[mt][nt][0] + b0;
                cp0[1] = acc[mt][nt][1] + b1;
                cp1[0] = acc[mt][nt][2] + b0;
                cp1[1] = acc[mt][nt][3] + b1;
            }
        }
    }
}

// ---------------- scalar attention kernels ----------------
__global__ void k_pool(const float* __restrict__ lin, float* __restrict__ A) {
    const int a = blockIdx.x;
    const int c = threadIdx.x;
    const int p1 = a >> 4, p2 = (a >> 2) & 3, p3 = a & 3;
    const int csub = c >> 5;
    float s = 0.0f;
    for (int b1 = 0; b1 < 8; b1++) {
        const int f1 = p1 * 8 + b1;
        const int ch = (f1 >> 2) * 32 + (c & 31);
        const int nb1 = (f1 & 3) * 8192;
        for (int b2 = 0; b2 < 8; b2++) {
            const int nb2 = nb1 + (p2 * 8 + b2) * 256;
            for (int b3 = 0; b3 < 8; b3++) {
                const int n = nb2 + (p3 * 8 + b3) * 8 + csub;
                s += lin[(size_t)n * 768 + ch];
            }
        }
    }
    A[a * 256 + c] = s * (1.0f / 512.0f);
}

__global__ void __launch_bounds__(256) k_S(const float* __restrict__ lin,
                                           const float* __restrict__ Amat,
                                           float* __restrict__ S) {
    const int h = blockIdx.y;
    const int n = blockIdx.x * 256 + threadIdx.x;
    __shared__ float4 As[64][8];
    for (int e = threadIdx.x; e < 512; e += 256) {
        int a = e >> 3, dq = e & 7;
        As[a][dq] = *(const float4*)&Amat[a * 256 + h * 32 + dq * 4];
    }
    __syncthreads();
    float4 kv[8];
    const float* kp = lin + (size_t)n * 768 + 256 + h * 32;
#pragma unroll
    for (int i = 0; i < 8; i++) kv[i] = *(const float4*)&kp[i * 4];
    const float scale = 0.17677669529663687f;
    float* Sp = S + (size_t)(h * 64) * NTOK + n;
#pragma unroll 4
    for (int a = 0; a < 64; a++) {
        float s = 0.0f;
#pragma unroll
        for (int i = 0; i < 8; i++) {
            const float4 av = As[a][i];
            s += kv[i].x * av.x + kv[i].y * av.y + kv[i].z * av.z + kv[i].w * av.w;
        }
        Sp[(size_t)a * NTOK] = s * scale;
    }
}

// pass 1: row max; pass 2: P = exp(S-m) written back into S, l = sum P
__global__ void k_rowstat(float* __restrict__ S, float* __restrict__ l) {
    const int r = blockIdx.x;
    float4* Sr = (float4*)(S + (size_t)r * NTOK);
    __shared__ float red[256];
    float mx = -1e30f;
    for (int i = threadIdx.x; i < NTOK / 4; i += 256) {
        float4 v = Sr[i];
        mx = fmaxf(mx, fmaxf(fmaxf(v.x, v.y), fmaxf(v.z, v.w)));
    }
    red[threadIdx.x] = mx; __syncthreads();
    for (int s = 128; s > 0; s >>= 1) {
        if (threadIdx.x < s) red[threadIdx.x] = fmaxf(red[threadIdx.x], red[threadIdx.x + s]);
        __syncthreads();
    }
    mx = red[0]; __syncthreads();
    float sum = 0.0f;
    for (int i = threadIdx.x; i < NTOK / 4; i += 256) {
        float4 v = Sr[i];
        v.x = fexp(v.x - mx); v.y = fexp(v.y - mx);
        v.z = fexp(v.z - mx); v.w = fexp(v.w - mx);
        Sr[i] = v;
        sum += v.x + v.y + v.z + v.w;
    }
    red[threadIdx.x] = sum; __syncthreads();
    for (int s = 128; s > 0; s >>= 1) {
        if (threadIdx.x < s) red[threadIdx.x] += red[threadIdx.x + s];
        __syncthreads();
    }
    if (threadIdx.x == 0) l[r] = red[0];
}

// agent_v partials; S already holds P = exp(S - m)
__global__ void __launch_bounds__(256) k_agentv(const float* __restrict__ lin,
                                                const float* __restrict__ S,
                                                float* __restrict__ part) {
    const int h = blockIdx.y;
    const int chunk = blockIdx.x;
    const int n0 = chunk * 512;
    __shared__ float Ss[64][64];
    __shared__ float vs[64][32];
    const int a = threadIdx.x >> 2, dg = threadIdx.x & 3;
    float4 acc0 = {0, 0, 0, 0}, acc1 = {0, 0, 0, 0};

    for (int sub = 0; sub < 8; sub++) {
        const int nb = n0 + sub * 64;
        for (int e = threadIdx.x; e < 1024; e += 256) {
            int aa = e >> 4, tq = e & 15;
            *(float4*)&Ss[aa][tq * 4] =
                *(const float4*)&S[(size_t)(h * 64 + aa) * NTOK + nb + tq * 4];
        }
        for (int e = threadIdx.x; e < 512; e += 256) {
            int tt = e >> 3, dq = e & 7;
            *(float4*)&vs[tt][dq * 4] =
                *(const float4*)&lin[(size_t)(nb + tt) * 768 + 512 + h * 32 + dq * 4];
        }
        __syncthreads();
#pragma unroll 8
        for (int tt = 0; tt < 64; tt++) {
            const float p = Ss[a][tt];
            const float4 v0 = *(const float4*)&vs[tt][dg * 8];
            const float4 v1 = *(const float4*)&vs[tt][dg * 8 + 4];
            acc0.x += p * v0.x; acc0.y += p * v0.y; acc0.z += p * v0.z; acc0.w += p * v0.w;
            acc1.x += p * v1.x; acc1.y += p * v1.y; acc1.z += p * v1.z; acc1.w += p * v1.w;
        }
        __syncthreads();
    }
    float* pp = part + (size_t)((chunk * 8 + h) * 64 + a) * 32 + dg * 8;
    *(float4*)pp = acc0;
    *(float4*)(pp + 4) = acc1;
}

__global__ void k_avreduce(const float* __restrict__ part, const float* __restrict__ l,
                           float* __restrict__ av) {
    const int idx = blockIdx.x * 256 + threadIdx.x;
    float s = 0.0f;
    for (int ch = 0; ch < 64; ch++) s += part[(size_t)ch * 16384 + idx];
    av[idx] = s / l[idx >> 5];
}

__global__ void __launch_bounds__(256) k_stage2(const float* __restrict__ lin,
                                                const float* __restrict__ Amat,
                                                const float* __restrict__ av,
                                                float* __restrict__ mid) {
    const int h = blockIdx.y;
    const int n = blockIdx.x * 256 + threadIdx.x;
    __shared__ float4 As[64][8];
    __shared__ float4 Vs[64][8];
    for (int e = threadIdx.x; e < 512; e += 256) {
        int a = e >> 3, dq = e & 7;
        As[a][dq] = *(const float4*)&Amat[a * 256 + h * 32 + dq * 4];
        Vs[a][dq] = *(const float4*)&av[(size_t)(h * 64 + a) * 32 + dq * 4];
    }
    __syncthreads();
    float4 qv[8];
    const float* qp = lin + (size_t)n * 768 + h * 32;
#pragma unroll
    for (int i = 0; i < 8; i++) qv[i] = *(const float4*)&qp[i * 4];
    const float scale = 0.17677669529663687f;
    float lg[64];
    float mx = -1e30f;
#pragma unroll
    for (int a = 0; a < 64; a++) {
        float s = 0.0f;
#pragma unroll
        for (int i = 0; i < 8; i++) {
            const float4 v = As[a][i];
            s += qv[i].x * v.x + qv[i].y * v.y + qv[i].z * v.z + qv[i].w * v.w;
        }
        s *= scale;
        lg[a] = s;
        mx = fmaxf(mx, s);
    }
    float sum = 0.0f;
#pragma unroll
    for (int a = 0; a < 64; a++) {
        const float p = fexp(lg[a] - mx);
        lg[a] = p;
        sum += p;
    }
    float4 o[8];
#pragma unroll
    for (int i = 0; i < 8; i++) { o[i].x = 0; o[i].y = 0; o[i].z = 0; o[i].w = 0; }
#pragma unroll
    for (int a = 0; a < 64; a++) {
        const float p = lg[a];
#pragma unroll
        for (int i = 0; i < 8; i++) {
            const float4 v = Vs[a][i];
            o[i].x += p * v.x; o[i].y += p * v.y; o[i].z += p * v.z; o[i].w += p * v.w;
        }
    }
    const float inv = 1.0f / sum;
    float* mp = mid + (size_t)h * 1048576 + n;
#pragma unroll
    for (int i = 0; i < 8; i++) {
        mp[(size_t)(i * 4 + 0) * NTOK] = o[i].x * inv;
        mp[(size_t)(i * 4 + 1) * NTOK] = o[i].y * inv;
        mp[(size_t)(i * 4 + 2) * NTOK] = o[i].z * inv;
        mp[(size_t)(i * 4 + 3) * NTOK] = o[i].w * inv;
    }
}

// ---------------- launch ----------------
extern "C" void kernel_launch(void* const* d_in, const int* in_sizes, int n_in,
                              void* d_out, int out_size) {
    const float* x      = (const float*)d_in[0];
    const float* w_qkv  = (const float*)d_in[1];
    const float* b_qkv  = (const float*)d_in[2];
    const float* w_proj = (const float*)d_in[3];
    const float* b_proj = (const float*)d_in[4];
    const float* w_dwc  = (const float*)d_in[5];
    const float* b_dwc  = (const float*)d_in[6];
    float* out = (float*)d_out;

    float *lin, *S, *l, *A, *avpart, *av, *mid;
    __nv_bfloat16 *xhi, *xlo, *mhi, *mlo, *vph, *vpl, *wqh, *wql, *wph, *wpl, *wch, *wcl;
    cudaGetSymbolAddress((void**)&lin,    g_lin);
    cudaGetSymbolAddress((void**)&S,      g_S);
    cudaGetSymbolAddress((void**)&l,      g_l);
    cudaGetSymbolAddress((void**)&A,      g_A);
    cudaGetSymbolAddress((void**)&avpart, g_avpart);
    cudaGetSymbolAddress((void**)&av,     g_av);
    cudaGetSymbolAddress((void**)&mid,    g_mid);
    cudaGetSymbolAddress((void**)&xhi,    g_xhi);
    cudaGetSymbolAddress((void**)&xlo,    g_xlo);
    cudaGetSymbolAddress((void**)&mhi,    g_mhi);
    cudaGetSymbolAddress((void**)&mlo,    g_mlo);
    cudaGetSymbolAddress((void**)&vph,    g_vph);
    cudaGetSymbolAddress((void**)&vpl,    g_vpl);
    cudaGetSymbolAddress((void**)&wqh,    g_wqh);
    cudaGetSymbolAddress((void**)&wql,    g_wql);
    cudaGetSymbolAddress((void**)&wph,    g_wph);
    cudaGetSymbolAddress((void**)&wpl,    g_wpl);
    cudaGetSymbolAddress((void**)&wch,    g_wch);
    cudaGetSymbolAddress((void**)&wcl,    g_wcl);

    cudaFuncSetAttribute(gemm_mma, cudaFuncAttributeMaxDynamicSharedMemorySize, SMEM_TOT);

    // splits
    k_split<<<(NTOK * CDIM + 255) / 256, 256>>>(x, xhi, xlo, NTOK * CDIM);
    k_split<<<(768 * 256 + 255) / 256, 256>>>(w_qkv, wqh, wql, 768 * 256);
    k_split<<<(256 * 256 + 255) / 256, 256>>>(w_proj, wph, wpl, 256 * 256);
    k_wconv<<<(27 * 256 * 256) / 256, 256>>>(w_dwc, wch, wcl);
    k_zero_b<<<(PVOL * CDIM / 2 + 255) / 256, 256>>>((uint32_t*)vph, PVOL * CDIM / 2);
    k_zero_b<<<(PVOL * CDIM / 2 + 255) / 256, 256>>>((uint32_t*)vpl, PVOL * CDIM / 2);

    // qkv projection: lin = x @ w_qkv^T + b
    gemm_mma<<<dim3(6, 256), 256, SMEM_TOT>>>(xhi, xlo, wqh, wql, b_qkv, lin, 256, 768, 0, 0);

    // attention
    k_pool<<<64, 256>>>(lin, A);
    k_S<<<dim3(128, 8), 256>>>(lin, A, S);
    k_rowstat<<<512, 256>>>(S, l);
    k_agentv<<<dim3(64, 8), 256>>>(lin, S, avpart);
    k_avreduce<<<64, 256>>>(avpart, l, av);
    k_stage2<<<dim3(128, 8), 256>>>(lin, A, av, mid);

    // conv residual (implicit GEMM), accumulate into mid
    k_vpadsplit<<<NTOK, 64>>>(lin, vph, vpl);
    gemm_mma<<<dim3(2, 256), 256, SMEM_TOT>>>(vph, vpl, wch, wcl, b_dwc, mid, KCONV, 256, 1, 1);

    // output projection
    k_split<<<(NTOK * CDIM + 255) / 256, 256>>>(mid, mhi, mlo, NTOK * CDIM);
    gemm_mma<<<dim3(2, 256), 256, SMEM_TOT>>>(mhi, mlo, wph, wpl, b_proj, out, 256, 256, 0, 0);
}